// round 9
// baseline (speedup 1.0000x reference)
#include <cuda_runtime.h>

#define NN    2048
#define DIN   128
#define HH    256
#define DEMB  64
#define NSTRIP 8
#define STRIPJ (NN / NSTRIP)   // 256
#define BI    64
#define BJ    64
#define RA    16               // rows per kA block
#define XPAD  20               // xsT/oxT row pad

// -------- device scratch (no allocations allowed) --------
__device__ __align__(16) float g_emb[NN * DEMB];            // 512 KB
__device__ __align__(16) float g_sq[NN];                    // 8 KB
__device__ __align__(16) float g_xlast[NN * DIN];           // 1 MB
__device__ __align__(16) float g_ypart[NSTRIP * NN * DIN];  // 8 MB
__device__ __align__(16) float g_degpart[NSTRIP * NN];      // 64 KB

// -------- packed fp32x2 helpers (exact fp32, 2 FMA / instr) --------
typedef unsigned long long ull;
__device__ __forceinline__ ull pk2(float a, float b) {
    ull r; asm("mov.b64 %0, {%1, %2};" : "=l"(r) : "f"(a), "f"(b)); return r;
}
__device__ __forceinline__ void fma2(ull& d, ull a, ull b) {
    asm("fma.rn.f32x2 %0, %1, %2, %0;" : "+l"(d) : "l"(a), "l"(b));
}
__device__ __forceinline__ float2 upk(ull v) {
    float2 f; asm("mov.b64 {%0, %1}, %2;" : "=f"(f.x), "=f"(f.y) : "l"(v)); return f;
}
__device__ __forceinline__ float sigmoidf(float z) {
    return 1.0f / (1.0f + __expf(-z));
}

// One k-range GEMM panel: acc[c] += x(rowpair) * W[k][4cg+c], batch-8
// double-buffered prefetch. wptr points at W + kbase*ldw + 4*cg;
// xptr at actT + kbase*XPAD + 2*rp. KITER multiple of 8.
template<int KITER, int LDW>
__device__ __forceinline__ void gemm_panel(
    const float* __restrict__ wptr, const float* __restrict__ xptr,
    ull& a0, ull& a1, ull& a2, ull& a3)
{
    float4 wb[8]; ull xb[8];
    #pragma unroll
    for (int u = 0; u < 8; u++) {
        wb[u] = *(const float4*)(wptr + u * LDW);
        xb[u] = *(const ull*)(xptr + u * XPAD);
    }
    #pragma unroll
    for (int kk = 0; kk < KITER; kk += 8) {
        float4 wn[8]; ull xn[8];
        if (kk + 8 < KITER) {
            #pragma unroll
            for (int u = 0; u < 8; u++) {
                wn[u] = *(const float4*)(wptr + (kk + 8 + u) * LDW);
                xn[u] = *(const ull*)(xptr + (kk + 8 + u) * XPAD);
            }
        }
        #pragma unroll
        for (int u = 0; u < 8; u++) {
            const ull xx = xb[u];
            fma2(a0, xx, pk2(wb[u].x, wb[u].x));
            fma2(a1, xx, pk2(wb[u].y, wb[u].y));
            fma2(a2, xx, pk2(wb[u].z, wb[u].z));
            fma2(a3, xx, pk2(wb[u].w, wb[u].w));
        }
        if (kk + 8 < KITER) {
            #pragma unroll
            for (int u = 0; u < 8; u++) { wb[u] = wn[u]; xb[u] = xn[u]; }
        }
    }
}

// ============================================================
// Kernel A: out_x = relu(x@W0+b0); emb = relu(out_x@W1+b1);
//           sq = rowsum(emb^2); x_last = x@W2+b2
// 128 blocks x 16 rows, 512 threads. Every stage: thread owns
// 4 cols x 1 rowpair -> 1 LDG.128 + 1 bcast LDS.64 + 4 FFMA2
// per k, deep-prefetched.
// ============================================================
__global__ void __launch_bounds__(512) kA(
    const float* __restrict__ x,
    const float* __restrict__ W0, const float* __restrict__ b0,
    const float* __restrict__ W1, const float* __restrict__ b1,
    const float* __restrict__ W2, const float* __restrict__ b2)
{
    extern __shared__ float sma[];
    float* xsT  = sma;                    // [128][20]
    float* oxT  = xsT + DIN * XPAD;       // [256][20]
    float* embS = oxT + HH * XPAD;        // [16][68]
    float* red3 = embS + RA * 68;         // [256][8]
    float* red2 = red3 + 256 * 8;         // [3][128][8]

    const int t = threadIdx.x;
    const int row0 = blockIdx.x * RA;

    // stage x rows transposed (k-major)
    #pragma unroll
    for (int idx = t; idx < RA * DIN; idx += 512) {
        const int r = idx >> 7, k = idx & 127;
        xsT[k * XPAD + r] = x[row0 * DIN + idx];
    }
    __syncthreads();

    // ---- stage 1: out_x [16,256]; thread = (cg 0..63, rp 0..7) ----
    {
        const int cg = t & 63;
        const int rp = t >> 6;
        ull a0 = 0, a1 = 0, a2 = 0, a3 = 0;
        gemm_panel<DIN, HH>(W0 + 4 * cg, xsT + 2 * rp, a0, a1, a2, a3);
        const float4 bb = *(const float4*)(b0 + 4 * cg);
        const float2 v0 = upk(a0), v1 = upk(a1), v2 = upk(a2), v3 = upk(a3);
        float* o = oxT + (4 * cg) * XPAD + 2 * rp;
        o[0] = fmaxf(v0.x + bb.x, 0.f); o[1] = fmaxf(v0.y + bb.x, 0.f);
        o += XPAD;
        o[0] = fmaxf(v1.x + bb.y, 0.f); o[1] = fmaxf(v1.y + bb.y, 0.f);
        o += XPAD;
        o[0] = fmaxf(v2.x + bb.z, 0.f); o[1] = fmaxf(v2.y + bb.z, 0.f);
        o += XPAD;
        o[0] = fmaxf(v3.x + bb.w, 0.f); o[1] = fmaxf(v3.y + bb.w, 0.f);
    }

    // ---- stage 3: x_last [16,128]; thread = (cg 0..31, rp 0..7, kh 0..1) ----
    ull s3a0 = 0, s3a1 = 0, s3a2 = 0, s3a3 = 0;
    {
        const int cg = t & 31;
        const int rp = (t >> 5) & 7;
        const int kh = t >> 8;
        gemm_panel<64, DIN>(W2 + (kh * 64) * DIN + 4 * cg,
                            xsT + (kh * 64) * XPAD + 2 * rp,
                            s3a0, s3a1, s3a2, s3a3);
        if (kh == 1) {
            float* rp3 = red3 + (t & 255) * 8;
            *(ull*)(rp3 + 0) = s3a0; *(ull*)(rp3 + 2) = s3a1;
            *(ull*)(rp3 + 4) = s3a2; *(ull*)(rp3 + 6) = s3a3;
        }
    }
    __syncthreads();   // oxT ready + red3 partials ready

    // stage-3 finalize (threads with kh==0)
    if (t < 256) {
        const int cg = t & 31;
        const int rp = t >> 5;
        const float* rp3 = red3 + t * 8;
        const float2 q0 = upk(*(const ull*)(rp3 + 0));
        const float2 q1 = upk(*(const ull*)(rp3 + 2));
        const float2 q2 = upk(*(const ull*)(rp3 + 4));
        const float2 q3 = upk(*(const ull*)(rp3 + 6));
        const float2 p0 = upk(s3a0), p1 = upk(s3a1);
        const float2 p2 = upk(s3a2), p3 = upk(s3a3);
        const float4 bb = *(const float4*)(b2 + 4 * cg);
        float4 o0, o1;
        o0.x = p0.x + q0.x + bb.x; o1.x = p0.y + q0.y + bb.x;
        o0.y = p1.x + q1.x + bb.y; o1.y = p1.y + q1.y + bb.y;
        o0.z = p2.x + q2.x + bb.z; o1.z = p2.y + q2.y + bb.z;
        o0.w = p3.x + q3.x + bb.w; o1.w = p3.y + q3.y + bb.w;
        *(float4*)(g_xlast + (size_t)(row0 + 2 * rp) * DIN + 4 * cg)     = o0;
        *(float4*)(g_xlast + (size_t)(row0 + 2 * rp + 1) * DIN + 4 * cg) = o1;
    }

    // ---- stage 2: emb [16,64]; thread = (cg 0..15, rp 0..7, kq 0..3) ----
    {
        const int cg = t & 15;
        const int rp = (t >> 4) & 7;
        const int kq = t >> 7;
        ull a0 = 0, a1 = 0, a2 = 0, a3 = 0;
        gemm_panel<64, DEMB>(W1 + (kq * 64) * DEMB + 4 * cg,
                             oxT + (kq * 64) * XPAD + 2 * rp,
                             a0, a1, a2, a3);
        if (kq > 0) {
            float* rp2 = red2 + ((kq - 1) * 128 + (t & 127)) * 8;
            *(ull*)(rp2 + 0) = a0; *(ull*)(rp2 + 2) = a1;
            *(ull*)(rp2 + 4) = a2; *(ull*)(rp2 + 6) = a3;
        }
        __syncthreads();
        if (kq == 0) {
            float2 p[4] = {upk(a0), upk(a1), upk(a2), upk(a3)};
            #pragma unroll
            for (int sset = 0; sset < 3; sset++) {
                const float* rp2 = red2 + (sset * 128 + t) * 8;
                #pragma unroll
                for (int c = 0; c < 4; c++) {
                    const float2 q = upk(*(const ull*)(rp2 + 2 * c));
                    p[c].x += q.x; p[c].y += q.y;
                }
            }
            const float4 bb = *(const float4*)(b1 + 4 * cg);
            const float bbv[4] = {bb.x, bb.y, bb.z, bb.w};
            float4 e0, e1;
            float* ep0 = &e0.x; float* ep1 = &e1.x;
            #pragma unroll
            for (int c = 0; c < 4; c++) {
                ep0[c] = fmaxf(p[c].x + bbv[c], 0.f);
                ep1[c] = fmaxf(p[c].y + bbv[c], 0.f);
            }
            *(float4*)(g_emb + (size_t)(row0 + 2 * rp) * DEMB + 4 * cg)     = e0;
            *(float4*)(g_emb + (size_t)(row0 + 2 * rp + 1) * DEMB + 4 * cg) = e1;
            *(float4*)(embS + (2 * rp) * 68 + 4 * cg)     = e0;
            *(float4*)(embS + (2 * rp + 1) * 68 + 4 * cg) = e1;
        }
    }
    __syncthreads();

    // ---- sq ----
    if (t < RA) {
        float s = 0.f;
        #pragma unroll
        for (int e = 0; e < DEMB; e++) {
            const float v = embS[t * 68 + e];
            s = fmaf(v, v, s);
        }
        g_sq[row0 + t] = s;
    }
}

// ============================================================
// Kernel B: 64 i-rows x 256 j-cols strip of A per block.
//  GEMM1 (4x4/thread, FFMA2) -> sigmoid+eye epilogue -> adj +
//  GEMM2 (2 rows x 16 cols/thread, FFMA2, conflict-free cols).
// grid (8, 32) = 256 blocks, 2 blocks/SM.
// ============================================================
__global__ void __launch_bounds__(256, 2) kB(
    const float* __restrict__ tempp,
    const float* __restrict__ thetap,
    float* __restrict__ adj_out)
{
    extern __shared__ float sm[];
    float* embIs = sm;                    // [64][68] k-major
    float* embJs = embIs + 64 * 68;       // [64][68] k-major
    float* xls   = embJs + 64 * 68;       // [64][132] j-major, padded
    float* As    = xls + 64 * 132;        // [64][68]
    float* sqJs  = As + 64 * 68;          // [64]
    float* degsh = sqJs + 64;             // [64][16]

    const int t  = threadIdx.x;
    const int s  = blockIdx.x;            // strip
    const int i0 = blockIdx.y * BI;
    const int jstart = s * STRIPJ;

    const float c1 = 1.0f + *tempp;
    const float c2 = 5.0f + *thetap;

    // stage embI transposed (k-major)
    #pragma unroll
    for (int idx = t; idx < BI * DEMB; idx += 256) {
        const int k = idx & 63, r = idx >> 6;
        embIs[k * 68 + r] = g_emb[(i0 + r) * DEMB + k];
    }

    // GEMM1 coords: 4 rows x 4 cols per thread
    const int r0 = (t >> 4) * 4;
    const int c0 = (t & 15) * 4;
    const float4 sqI = *(const float4*)&g_sq[i0 + r0];
    float degA[4] = {0.f, 0.f, 0.f, 0.f};

    // GEMM2 coords: rows {2q, 2q+1}, cols {g*4 + 32u + 0..3}
    const int q = t >> 3;
    const int g = t & 7;
    ull yac[2][8];
    #pragma unroll
    for (int r = 0; r < 2; r++)
        #pragma unroll
        for (int p = 0; p < 8; p++) yac[r][p] = 0ULL;

    for (int cj = 0; cj < STRIPJ / BJ; cj++) {
        const int jb = jstart + cj * BJ;
        __syncthreads();   // prev-iter readers done before overwrite

        // stage embJ transposed
        #pragma unroll
        for (int idx = t; idx < BJ * DEMB; idx += 256) {
            const int k = idx & 63, jl = idx >> 6;
            embJs[k * 68 + jl] = g_emb[(jb + jl) * DEMB + k];
        }
        if (t < BJ) sqJs[t] = g_sq[jb + t];
        // stage x_last chunk [64][132-padded] via float4
        {
            const float4* src = (const float4*)(g_xlast + (size_t)jb * DIN);
            #pragma unroll
            for (int idx = t; idx < BJ * DIN / 4; idx += 256) {
                const int row = idx >> 5, c4 = idx & 31;
                *(float4*)&xls[row * 132 + c4 * 4] = src[idx];
            }
        }
        __syncthreads();

        // ---- GEMM1: 4x4 per thread over k=64, packed j-pairs ----
        ull acc[4][2];
        #pragma unroll
        for (int r = 0; r < 4; r++) { acc[r][0] = 0ULL; acc[r][1] = 0ULL; }
        #pragma unroll 4
        for (int k = 0; k < DEMB; k++) {
            const float4 ai = *(const float4*)&embIs[k * 68 + r0];
            const float4 bj = *(const float4*)&embJs[k * 68 + c0];
            const ull b01 = pk2(bj.x, bj.y);
            const ull b23 = pk2(bj.z, bj.w);
            ull aa;
            aa = pk2(ai.x, ai.x); fma2(acc[0][0], aa, b01); fma2(acc[0][1], aa, b23);
            aa = pk2(ai.y, ai.y); fma2(acc[1][0], aa, b01); fma2(acc[1][1], aa, b23);
            aa = pk2(ai.z, ai.z); fma2(acc[2][0], aa, b01); fma2(acc[2][1], aa, b23);
            aa = pk2(ai.w, ai.w); fma2(acc[3][0], aa, b01); fma2(acc[3][1], aa, b23);
        }

        // ---- epilogue: sigmoid + eye, write adj, stash A tile, deg ----
        {
            const float4 sqJ = *(const float4*)&sqJs[c0];
            const int jbase = jb + c0;
            const float si[4] = {sqI.x, sqI.y, sqI.z, sqI.w};
            #pragma unroll
            for (int rr = 0; rr < 4; rr++) {
                const float2 g0 = upk(acc[rr][0]);
                const float2 g1 = upk(acc[rr][1]);
                const float zi = si[rr];
                const int i = i0 + r0 + rr;
                float4 w;
                w.x = sigmoidf(fmaf(c1, 2.f * g0.x - zi - sqJ.x, c2));
                w.y = sigmoidf(fmaf(c1, 2.f * g0.y - zi - sqJ.y, c2));
                w.z = sigmoidf(fmaf(c1, 2.f * g1.x - zi - sqJ.z, c2));
                w.w = sigmoidf(fmaf(c1, 2.f * g1.y - zi - sqJ.w, c2));
                if (i == jbase)     w.x += 1.f;
                if (i == jbase + 1) w.y += 1.f;
                if (i == jbase + 2) w.z += 1.f;
                if (i == jbase + 3) w.w += 1.f;
                degA[rr] += (w.x + w.y) + (w.z + w.w);
                *(float4*)(adj_out + (size_t)i * NN + jbase) = w;
                *(float4*)&As[(r0 + rr) * 68 + c0] = w;
            }
        }
        __syncthreads();

        // ---- GEMM2: y[64][128] += A[64][64] @ xls[64][128] ----
        #pragma unroll 4
        for (int c = 0; c < BJ; c++) {
            const float a0 = As[(2 * q) * 68 + c];
            const float a1 = As[(2 * q + 1) * 68 + c];
            const ull A0 = pk2(a0, a0);
            const ull A1 = pk2(a1, a1);
            #pragma unroll
            for (int u = 0; u < 4; u++) {
                const float4 xv = *(const float4*)&xls[c * 132 + g * 4 + 32 * u];
                const ull x01 = pk2(xv.x, xv.y);
                const ull x23 = pk2(xv.z, xv.w);
                fma2(yac[0][2 * u],     A0, x01);
                fma2(yac[0][2 * u + 1], A0, x23);
                fma2(yac[1][2 * u],     A1, x01);
                fma2(yac[1][2 * u + 1], A1, x23);
            }
        }
    }

    // write y partials
    #pragma unroll
    for (int r = 0; r < 2; r++) {
        float* base = g_ypart + ((size_t)s * NN + i0 + 2 * q + r) * DIN;
        #pragma unroll
        for (int u = 0; u < 4; u++) {
            const float2 p0 = upk(yac[r][2 * u]);
            const float2 p1 = upk(yac[r][2 * u + 1]);
            *(float4*)(base + g * 4 + 32 * u) = make_float4(p0.x, p0.y, p1.x, p1.y);
        }
    }

    // deg reduction (deterministic)
    #pragma unroll
    for (int rr = 0; rr < 4; rr++)
        degsh[(r0 + rr) * 16 + (t & 15)] = degA[rr];
    __syncthreads();
    if (t < BI) {
        float sdeg = 0.f;
        #pragma unroll
        for (int gg = 0; gg < 16; gg++) sdeg += degsh[t * 16 + gg];
        g_degpart[s * NN + i0 + t] = sdeg;
    }
}

// ============================================================
// Kernel C: out = relu( (sum_s y_part) / (sum_s deg_part) )
// ============================================================
__global__ void __launch_bounds__(256) kC(float* __restrict__ out)
{
    const int idx = blockIdx.x * 256 + threadIdx.x;  // < N*DIN
    const int i = idx >> 7;
    const int d = idx & 127;
    float deg = 0.f;
    #pragma unroll
    for (int s = 0; s < NSTRIP; s++) deg += g_degpart[s * NN + i];
    float y = 0.f;
    #pragma unroll
    for (int s = 0; s < NSTRIP; s++)
        y += g_ypart[((size_t)s * NN + i) * DIN + d];
    out[idx] = fmaxf(y / deg, 0.f);
}

// ============================================================
extern "C" void kernel_launch(void* const* d_in, const int* in_sizes, int n_in,
                              void* d_out, int out_size)
{
    const float* x     = (const float*)d_in[0];
    // d_in[1] = adj : unused (only its shape matters in the reference)
    const float* W0    = (const float*)d_in[2];
    const float* b0    = (const float*)d_in[3];
    const float* W1    = (const float*)d_in[4];
    const float* b1    = (const float*)d_in[5];
    const float* W2    = (const float*)d_in[6];
    const float* b2    = (const float*)d_in[7];
    const float* temp  = (const float*)d_in[8];
    const float* theta = (const float*)d_in[9];

    float* out     = (float*)d_out;          // [N, DIN] first
    float* adj_out = out + NN * DIN;         // then [N*N] adjacency

    const int smemA = (DIN * XPAD + HH * XPAD + RA * 68
                       + 256 * 8 + 3 * 128 * 8) * 4;
    cudaFuncSetAttribute(kA, cudaFuncAttributeMaxDynamicSharedMemorySize, smemA);
    kA<<<NN / RA, 512, smemA>>>(x, W0, b0, W1, b1, W2, b2);

    const int smemB = (64 * 68 + 64 * 68 + 64 * 132 + 64 * 68 + 64 + 64 * 16) * 4;
    cudaFuncSetAttribute(kB, cudaFuncAttributeMaxDynamicSharedMemorySize, smemB);
    dim3 gB(NSTRIP, NN / BI);
    kB<<<gB, 256, smemB>>>(temp, theta, adj_out);

    kC<<<NN * DIN / 256, 256>>>(out);
}